// round 1
// baseline (speedup 1.0000x reference)
#include <cuda_runtime.h>
#include <cstdint>

// Problem constants
#define B_     8
#define CDIM   64
#define NPOS   9216      // 96*96
#define INNER  128
#define O3     384       // 3*INNER
#define HEADS  4
#define DHEAD  32
#define NCH    9
#define CHUNK  1024
#define NTILE  256       // spatial tile for K1/K3/K4
#define NTILES 36        // NPOS / NTILE

// Scratch (device globals — no allocations allowed)
__device__ __align__(16) float g_qkv[(size_t)B_ * O3 * NPOS];      // [b][o][n]
__device__ __align__(16) float g_attn[(size_t)B_ * INNER * NPOS];  // [b][ic][n]
__device__ float g_part[B_][8][NTILES][2];                          // groupnorm partials

// ---------------------------------------------------------------------------
// K1: qkv[b][o][n] = sum_c W_qkv[o][c] * x[b][c][n]
// grid (36, 8), 256 threads; W in dynamic smem (96KB), x column in registers.
// ---------------------------------------------------------------------------
__global__ __launch_bounds__(256, 2) void qkv_kernel(const float* __restrict__ x,
                                                     const float* __restrict__ Wq) {
    extern __shared__ float sW[];  // O3*CDIM floats
    const int b = blockIdx.y, n0 = blockIdx.x * NTILE, tid = threadIdx.x;

    for (int i = tid; i < O3 * CDIM; i += 256) sW[i] = Wq[i];
    __syncthreads();

    const float* xb = x + (size_t)b * CDIM * NPOS + n0 + tid;
    float xc[CDIM];
#pragma unroll
    for (int c = 0; c < CDIM; c++) xc[c] = xb[(size_t)c * NPOS];

    float* op = g_qkv + (size_t)b * O3 * NPOS + n0 + tid;
    for (int o = 0; o < O3; o++) {
        const float4* wr = (const float4*)(sW + o * CDIM);
        float acc = 0.f;
#pragma unroll
        for (int q = 0; q < CDIM / 4; q++) {
            float4 w = wr[q];
            acc += w.x * xc[4 * q] + w.y * xc[4 * q + 1] + w.z * xc[4 * q + 2] + w.w * xc[4 * q + 3];
        }
        op[(size_t)o * NPOS] = acc;
    }
}

// ---------------------------------------------------------------------------
// K2: per (g = b*4+head, ch) chunk attention, reassociated:
//   Eq[d][i] = exp(q - rowmax), Zq[d] = sum_i Eq
//   Ks[:,i]  = softmax over d (32 channels)
//   A[d][d'] = sum_i Eq[d][i]*Ks[d'][i];  out = diag(1/Zq) * A * V
// grid (9, 32), 256 threads, 168KB dynamic smem.
// ---------------------------------------------------------------------------
#define KVPAD 257
#define SMEM_ATTN ((32 * 1024 + 32 * KVPAD + 32 * 33 + 32) * 4)

__global__ __launch_bounds__(256, 1) void attn_kernel() {
    extern __shared__ float sm[];
    float* q_s  = sm;                        // [32][1024] -> holds Eq after stats
    float* kv_s = q_s + 32 * 1024;           // [32][257]
    float* A_s  = kv_s + 32 * KVPAD;         // [32][33]
    float* rinv = A_s + 32 * 33;             // [32] : 1/Zq

    const int g = blockIdx.y, ch = blockIdx.x;
    const int b = g >> 2, head = g & 3;
    const int tid = threadIdx.x, lane = tid & 31, wrp = tid >> 5;

    const float* qbase = g_qkv + ((size_t)(b * O3 + head * DHEAD)) * NPOS + ch * CHUNK;
    const float* kbase = qbase + (size_t)INNER * NPOS;
    const float* vbase = qbase + (size_t)(2 * INNER) * NPOS;

    // load q tile [32][1024] (float4, coalesced)
    for (int idx = tid; idx < 32 * 256; idx += 256) {
        int d = idx >> 8, c4 = idx & 255;
        ((float4*)q_s)[idx] = ((const float4*)(qbase + (size_t)d * NPOS))[c4];
    }
    __syncthreads();

    // row softmax stats: warp wrp owns rows wrp*4 .. wrp*4+3
    const int d0 = wrp * 4;
    for (int r = 0; r < 4; r++) {
        int d = d0 + r;
        float* row = q_s + d * 1024;
        float m = -1e30f;
        for (int c = lane; c < 1024; c += 32) m = fmaxf(m, row[c]);
        for (int off = 16; off; off >>= 1) m = fmaxf(m, __shfl_xor_sync(0xffffffffu, m, off));
        float s = 0.f;
        for (int c = lane; c < 1024; c += 32) {
            float e = __expf(row[c] - m);
            row[c] = e;
            s += e;
        }
        for (int off = 16; off; off >>= 1) s += __shfl_xor_sync(0xffffffffu, s, off);
        if (lane == 0) rinv[d] = 1.0f / s;
    }
    __syncthreads();

    // Phase A: A[d][d'] accumulation, streaming k subtiles of 256 positions
    float a0 = 0.f, a1 = 0.f, a2 = 0.f, a3 = 0.f;  // A[d0..d0+3][lane]
    for (int it = 0; it < 4; it++) {
        for (int idx = tid; idx < 32 * 256; idx += 256) {
            int d = idx >> 8, c = idx & 255;
            kv_s[d * KVPAD + c] = kbase[(size_t)d * NPOS + it * 256 + c];
        }
        __syncthreads();
        {   // column softmax over d=0..31 ; thread tid owns column tid
            int j = tid;
            float m = -1e30f;
#pragma unroll
            for (int d = 0; d < 32; d++) m = fmaxf(m, kv_s[d * KVPAD + j]);
            float s = 0.f;
#pragma unroll
            for (int d = 0; d < 32; d++) {
                float e = __expf(kv_s[d * KVPAD + j] - m);
                kv_s[d * KVPAD + j] = e;
                s += e;
            }
            float inv = 1.0f / s;
#pragma unroll
            for (int d = 0; d < 32; d++) kv_s[d * KVPAD + j] *= inv;
        }
        __syncthreads();
        // accumulate: Eq rows broadcast, Ks row per lane (conflict-free)
        const float* qr0 = q_s + (d0 + 0) * 1024 + it * 256;
        const float* qr1 = q_s + (d0 + 1) * 1024 + it * 256;
        const float* qr2 = q_s + (d0 + 2) * 1024 + it * 256;
        const float* qr3 = q_s + (d0 + 3) * 1024 + it * 256;
        const float* kl = kv_s + lane * KVPAD;
#pragma unroll 4
        for (int i = 0; i < 256; i++) {
            float kv = kl[i];
            a0 += qr0[i] * kv;
            a1 += qr1[i] * kv;
            a2 += qr2[i] * kv;
            a3 += qr3[i] * kv;
        }
        __syncthreads();
    }

    // finalize A (apply q-softmax denominator)
    A_s[(d0 + 0) * 33 + lane] = a0 * rinv[d0 + 0];
    A_s[(d0 + 1) * 33 + lane] = a1 * rinv[d0 + 1];
    A_s[(d0 + 2) * 33 + lane] = a2 * rinv[d0 + 2];
    A_s[(d0 + 3) * 33 + lane] = a3 * rinv[d0 + 3];
    __syncthreads();

    // Phase B: out = A * V, streaming v subtiles
    for (int it = 0; it < 4; it++) {
        for (int idx = tid; idx < 32 * 256; idx += 256) {
            int d = idx >> 8, c = idx & 255;
            kv_s[d * KVPAD + c] = vbase[(size_t)d * NPOS + it * 256 + c];
        }
        __syncthreads();
        float vcol[32];
#pragma unroll
        for (int dp = 0; dp < 32; dp++) vcol[dp] = kv_s[dp * KVPAD + tid];
        float* ob = g_attn + ((size_t)(b * INNER + head * DHEAD)) * NPOS + ch * CHUNK + it * 256 + tid;
        for (int d = 0; d < 32; d++) {
            const float* Ar = A_s + d * 33;
            float acc = 0.f;
#pragma unroll
            for (int dp = 0; dp < 32; dp++) acc += Ar[dp] * vcol[dp];
            ob[(size_t)d * NPOS] = acc;
        }
        __syncthreads();
    }
}

// ---------------------------------------------------------------------------
// K3: y = W_out @ attn + b_out, plus deterministic per-tile groupnorm partials
// grid (36, 8), 256 threads
// ---------------------------------------------------------------------------
__global__ __launch_bounds__(256, 1) void out_proj_kernel(const float* __restrict__ Wout,
                                                          const float* __restrict__ bout,
                                                          float* __restrict__ y) {
    __shared__ float sW[CDIM * INNER];     // 32KB
    __shared__ float swp[8][8][2];
    const int b = blockIdx.y, n0 = blockIdx.x * NTILE, tid = threadIdx.x;

    for (int i = tid; i < CDIM * INNER; i += 256) sW[i] = Wout[i];
    __syncthreads();

    const float* ab = g_attn + (size_t)b * INNER * NPOS + n0 + tid;
    float a[INNER];
#pragma unroll
    for (int ic = 0; ic < INNER; ic++) a[ic] = ab[(size_t)ic * NPOS];

    float gs[8], gq[8];
#pragma unroll
    for (int g = 0; g < 8; g++) { gs[g] = 0.f; gq[g] = 0.f; }

    float* yp = y + (size_t)b * CDIM * NPOS + n0 + tid;
    for (int o = 0; o < CDIM; o++) {
        const float4* wr = (const float4*)(sW + o * INNER);
        float acc = __ldg(bout + o);
#pragma unroll
        for (int q = 0; q < INNER / 4; q++) {
            float4 w = wr[q];
            acc += w.x * a[4 * q] + w.y * a[4 * q + 1] + w.z * a[4 * q + 2] + w.w * a[4 * q + 3];
        }
        yp[(size_t)o * NPOS] = acc;
        int g = o >> 3;
        gs[g] += acc;
        gq[g] += acc * acc;
    }

    const int lane = tid & 31, w = tid >> 5;
#pragma unroll
    for (int g = 0; g < 8; g++) {
        float s = gs[g], q = gq[g];
        for (int off = 16; off; off >>= 1) {
            s += __shfl_xor_sync(0xffffffffu, s, off);
            q += __shfl_xor_sync(0xffffffffu, q, off);
        }
        if (lane == 0) { swp[w][g][0] = s; swp[w][g][1] = q; }
    }
    __syncthreads();
    if (tid < 16) {
        int g = tid >> 1, qq = tid & 1;
        float s = 0.f;
#pragma unroll
        for (int ww = 0; ww < 8; ww++) s += swp[ww][g][qq];
        g_part[b][g][blockIdx.x][qq] = s;
    }
}

// ---------------------------------------------------------------------------
// K4: reduce partials (redundantly per CTA, deterministic), normalize in place
// grid (36, 8), 256 threads
// ---------------------------------------------------------------------------
__global__ void gnorm_kernel(float* __restrict__ y,
                             const float* __restrict__ gamma,
                             const float* __restrict__ beta) {
    __shared__ float tmp[8][2];
    __shared__ float mu[8], rs[8];
    const int b = blockIdx.y, n0 = blockIdx.x * NTILE, tid = threadIdx.x;

    if (tid < 16) {
        int g = tid >> 1, qq = tid & 1;
        float s = 0.f;
        for (int t = 0; t < NTILES; t++) s += g_part[b][g][t][qq];
        tmp[g][qq] = s;
    }
    __syncthreads();
    if (tid < 8) {
        const float invn = 1.0f / (8.0f * NPOS);
        float m = tmp[tid][0] * invn;
        float v = tmp[tid][1] * invn - m * m;
        mu[tid] = m;
        rs[tid] = rsqrtf(v + 1e-5f);
    }
    __syncthreads();

    float* yb = y + (size_t)b * CDIM * NPOS + n0 + tid;
    for (int c = 0; c < CDIM; c++) {
        float val = yb[(size_t)c * NPOS];
        int g = c >> 3;
        yb[(size_t)c * NPOS] = (val - mu[g]) * rs[g] * __ldg(gamma + c) + __ldg(beta + c);
    }
}

// ---------------------------------------------------------------------------
extern "C" void kernel_launch(void* const* d_in, const int* in_sizes, int n_in,
                              void* d_out, int out_size) {
    const float* x     = (const float*)d_in[0];
    const float* Wqkv  = (const float*)d_in[1];
    const float* Wout  = (const float*)d_in[2];
    const float* bout  = (const float*)d_in[3];
    const float* gamma = (const float*)d_in[4];
    const float* beta  = (const float*)d_in[5];
    float* y = (float*)d_out;

    cudaFuncSetAttribute(qkv_kernel, cudaFuncAttributeMaxDynamicSharedMemorySize, O3 * CDIM * 4);
    cudaFuncSetAttribute(attn_kernel, cudaFuncAttributeMaxDynamicSharedMemorySize, SMEM_ATTN);

    qkv_kernel<<<dim3(NTILES, B_), 256, O3 * CDIM * 4>>>(x, Wqkv);
    attn_kernel<<<dim3(NCH, 32), 256, SMEM_ATTN>>>();
    out_proj_kernel<<<dim3(NTILES, B_), 256>>>(Wout, bout, y);
    gnorm_kernel<<<dim3(NTILES, B_), 256>>>(y, gamma, beta);
}